// round 2
// baseline (speedup 1.0000x reference)
#include <cuda_runtime.h>
#include <cuda_bf16.h>
#include <cstdint>

// ---------------------------------------------------------------------------
// APD2Net: graph_conv == 3x3 SAME conv (weights (O,C,9), k=ky*3+kx),
// graph_pool == 2x2 spatial maxpool. Everything stays NCHW.
//
// R2: L1-bound fix. All smem reads are conflict-free LDS.128; math uses
// packed fma.rn.f32x2 (2 MAC/issue). Weights stored in smem pre-duplicated
// as (w,w) f32 pairs with a bank swizzle so the 8 oc-groups hit disjoint banks.
// ---------------------------------------------------------------------------

__device__ float g_bufA[2u * 64u * 384u * 384u];
__device__ float g_bufB[2u * 64u * 384u * 384u];

__device__ __forceinline__ unsigned long long fma2(unsigned long long a,
                                                   unsigned long long b,
                                                   unsigned long long c) {
    unsigned long long d;
    asm("fma.rn.f32x2 %0, %1, %2, %3;" : "=l"(d) : "l"(a), "l"(b), "l"(c));
    return d;
}
__device__ __forceinline__ unsigned long long pack2(float lo, float hi) {
    unsigned long long d;
    asm("mov.b64 %0, {%1, %2};" : "=l"(d) : "f"(lo), "f"(hi));
    return d;
}
__device__ __forceinline__ float2 unpack2(unsigned long long v) {
    float2 r;
    asm("mov.b64 {%0, %1}, %2;" : "=f"(r.x), "=f"(r.y) : "l"(v));
    return r;
}

// bank swizzle for the duplicated-weight row: 8 oc-groups -> banks 0,4,..,28
__device__ __forceinline__ int foff(int ocg) {
    return ocg * 16 + ((ocg >> 1) & 3) * 4;
}

// ---------------------------------------------------------------------------
// Tiled conv3x3 + bias + relu. Block: 256 thr. Tile: 64 oc x (8 x 16) px.
// Per-thread: 8 oc x 4 px, accumulated as 8 x 2 f32x2 pairs.
// ---------------------------------------------------------------------------
template <int CIN, int COUT, int CHUNK>
__global__ void __launch_bounds__(256, 2)
conv3x3_bias_relu(const float* __restrict__ in,
                  const float* __restrict__ wgt,
                  const float* __restrict__ bias,
                  float* __restrict__ out,
                  int H, int W)
{
    static_assert(CIN % CHUNK == 0, "CIN divisible by CHUNK");
    constexpr int TH = 8;
    constexpr int TW = 16;
    constexpr int OCB = 64;
    constexpr int WROW = 140;   // >= foff(7)+16 = 140; multiple of 4 (16B aligned)
    constexpr int IROW = 20;    // (TW+2)=18 padded to 20 for float4 alignment

    __shared__ __align__(16) float wsm[CHUNK][9][WROW];        // duplicated pairs
    __shared__ __align__(16) float insm[CHUNK][TH + 2][IROW];

    const int tiles_x = W / TW;
    const int bx = (blockIdx.x % tiles_x) * TW;
    const int by = (blockIdx.x / tiles_x) * TH;
    const int n  = blockIdx.y;
    const int oc_base = blockIdx.z * OCB;

    const int tid = threadIdx.x;
    const int ocg = tid & 7;
    const int pg  = tid >> 3;
    const int row = pg >> 2;
    const int col = (pg & 3) * 4;
    const int woff = foff(ocg);

    unsigned long long acc[8][2];
    #pragma unroll
    for (int o = 0; o < 8; ++o) { acc[o][0] = 0ull; acc[o][1] = 0ull; }

    #pragma unroll 1
    for (int c0 = 0; c0 < CIN; c0 += CHUNK) {
        // ---- weights: gmem (coalesced per-oc rows) -> smem duplicated pairs
        {
            const float* wg = wgt + (size_t)oc_base * CIN * 9 + (size_t)c0 * 9;
            constexpr int PER_OC = CHUNK * 9;
            constexpr int TOT = OCB * PER_OC;
            for (int idx = tid; idx < TOT; idx += 256) {
                int oc = idx / PER_OC;
                int r  = idx % PER_OC;                 // r = c*9 + k
                float v = wg[(size_t)oc * CIN * 9 + r];
                float2* dst = reinterpret_cast<float2*>(
                    &wsm[r / 9][r % 9][foff(oc >> 3) + (oc & 7) * 2]);
                *dst = make_float2(v, v);
            }
        }
        // ---- input tile: CHUNK x (TH+2) x 18 used cols, zero-padded borders
        {
            constexpr int ROWE = TW + 2;               // 18 used columns
            constexpr int TILE2D = (TH + 2) * ROWE;
            constexpr int TOT = CHUNK * TILE2D;
            for (int idx = tid; idx < TOT; idx += 256) {
                int c   = idx / TILE2D;
                int rem = idx % TILE2D;
                int iy  = rem / ROWE;
                int ix  = rem % ROWE;
                int gy = by + iy - 1;
                int gx = bx + ix - 1;
                float v = 0.0f;
                if (gy >= 0 && gy < H && gx >= 0 && gx < W)
                    v = in[(((size_t)n * CIN + c0 + c) * H + gy) * W + gx];
                insm[c][iy][ix] = v;
            }
        }
        __syncthreads();

        // ---- compute
        #pragma unroll 2
        for (int c = 0; c < CHUNK; ++c) {
            #pragma unroll
            for (int ky = 0; ky < 3; ++ky) {
                const float* rp = &insm[c][row + ky][col];
                float4 a  = *reinterpret_cast<const float4*>(rp);
                float4 bq = *reinterpret_cast<const float4*>(rp + 4);
                unsigned long long P[5];
                P[0] = pack2(a.x, a.y);
                P[1] = pack2(a.y, a.z);
                P[2] = pack2(a.z, a.w);
                P[3] = pack2(a.w, bq.x);
                P[4] = pack2(bq.x, bq.y);
                #pragma unroll
                for (int kx = 0; kx < 3; ++kx) {
                    const float* wp = &wsm[c][ky * 3 + kx][woff];
                    unsigned long long w2[8];
                    #pragma unroll
                    for (int j = 0; j < 4; ++j) {
                        ulonglong2 u = *reinterpret_cast<const ulonglong2*>(wp + 4 * j);
                        w2[2 * j]     = u.x;
                        w2[2 * j + 1] = u.y;
                    }
                    #pragma unroll
                    for (int o = 0; o < 8; ++o) {
                        acc[o][0] = fma2(w2[o], P[kx],     acc[o][0]);
                        acc[o][1] = fma2(w2[o], P[kx + 2], acc[o][1]);
                    }
                }
            }
        }
        __syncthreads();
    }

    // ---- epilogue: bias + relu, float4 stores
    const int gy = by + row;
    const int gx = bx + col;
    #pragma unroll
    for (int o = 0; o < 8; ++o) {
        const int oc = oc_base + ocg * 8 + o;
        const float b = bias[oc];
        float2 u0 = unpack2(acc[o][0]);
        float2 u1 = unpack2(acc[o][1]);
        float4 v;
        v.x = fmaxf(u0.x + b, 0.0f);
        v.y = fmaxf(u0.y + b, 0.0f);
        v.z = fmaxf(u1.x + b, 0.0f);
        v.w = fmaxf(u1.y + b, 0.0f);
        float* dst = out + (((size_t)n * COUT + oc) * H + gy) * W + gx;
        *reinterpret_cast<float4*>(dst) = v;
    }
}

// ---------------------------------------------------------------------------
// 2x2 maxpool, NCHW.
// ---------------------------------------------------------------------------
__global__ void maxpool2x2(const float* __restrict__ in,
                           float* __restrict__ out,
                           int total, int C, int Ho, int Wo)
{
    int idx = blockIdx.x * blockDim.x + threadIdx.x;
    if (idx >= total) return;
    int x = idx % Wo;
    int y = (idx / Wo) % Ho;
    int rest = idx / (Wo * Ho);
    const int Wi = 2 * Wo;
    const float* p = in + ((size_t)rest * (2 * Ho) + 2 * y) * Wi + 2 * x;
    float m = fmaxf(fmaxf(p[0], p[1]), fmaxf(p[Wi], p[Wi + 1]));
    out[idx] = m;
}

// ---------------------------------------------------------------------------
template <int CIN, int COUT, int CHUNK>
static inline void launch_conv(const float* in, const float* w, const float* b,
                               float* out, int H, int W, int N)
{
    dim3 grid((W / 16) * (H / 8), N, COUT / 64);
    conv3x3_bias_relu<CIN, COUT, CHUNK><<<grid, 256>>>(in, w, b, out, H, W);
}

static inline void launch_pool(const float* in, float* out, int N, int C, int Hi, int Wi)
{
    int Ho = Hi / 2, Wo = Wi / 2;
    int total = N * C * Ho * Wo;
    maxpool2x2<<<(total + 255) / 256, 256>>>(in, out, total, C, Ho, Wo);
}

extern "C" void kernel_launch(void* const* d_in, const int* in_sizes, int n_in,
                              void* d_out, int out_size)
{
    (void)in_sizes; (void)n_in; (void)out_size;

    const float* x = (const float*)d_in[0];          // (2,3,384,384)
    const float* w[11];
    const float* b[11];
    for (int k = 1; k <= 10; ++k) {
        w[k] = (const float*)d_in[2 + 2 * (k - 1)];
        b[k] = (const float*)d_in[3 + 2 * (k - 1)];
    }

    float* A;
    float* Bb;
    cudaGetSymbolAddress((void**)&A,  g_bufA);
    cudaGetSymbolAddress((void**)&Bb, g_bufB);
    float* O = (float*)d_out;
    const int N = 2;

    // Stage 1 @ 384x384
    launch_conv<3,   64, 3>(x,  w[1], b[1], A,  384, 384, N);
    launch_conv<64,  64, 8>(A,  w[2], b[2], Bb, 384, 384, N);
    launch_pool(Bb, A, N, 64, 384, 384);              // -> 192x192

    // Stage 2 @ 192x192
    launch_conv<64, 128, 8>(A,  w[3], b[3], Bb, 192, 192, N);
    launch_conv<128,128, 8>(Bb, w[4], b[4], A,  192, 192, N);
    launch_pool(A, Bb, N, 128, 192, 192);             // -> 96x96

    // Stage 3 @ 96x96
    launch_conv<128,256, 8>(Bb, w[5], b[5], A,  96, 96, N);
    launch_conv<256,256, 8>(A,  w[6], b[6], Bb, 96, 96, N);
    launch_conv<256,256, 8>(Bb, w[7], b[7], A,  96, 96, N);
    launch_pool(A, Bb, N, 256, 96, 96);               // -> 48x48

    // Stage 4 @ 48x48
    launch_conv<256,512, 8>(Bb, w[8],  b[8],  A,  48, 48, N);
    launch_conv<512,512, 8>(A,  w[9],  b[9],  Bb, 48, 48, N);
    launch_conv<512,512, 8>(Bb, w[10], b[10], O,  48, 48, N);
}

// round 3
// speedup vs baseline: 1.5173x; 1.5173x over previous
#include <cuda_runtime.h>
#include <cuda_bf16.h>
#include <cstdint>

// ---------------------------------------------------------------------------
// APD2Net: graph_conv == 3x3 SAME conv (weights (O,C,9), k=ky*3+kx),
// graph_pool == 2x2 spatial maxpool. Everything stays NCHW.
//
// R3: f32x2 FMA with OC-paired lanes. Weights read from smem as natural
// (w_2o, w_2o+1) pairs via conflict-free LDS.64 (non-duplicated). Inputs read
// as scalar broadcast LDS and duplicated into (x,x) with one mov each.
// Per-thread tile: 8 oc x 8 px. FMA-pipe-bound by design.
// ---------------------------------------------------------------------------

__device__ float g_bufA[2u * 64u * 384u * 384u];
__device__ float g_bufB[2u * 64u * 384u * 384u];

__device__ __forceinline__ unsigned long long fma2(unsigned long long a,
                                                   unsigned long long b,
                                                   unsigned long long c) {
    unsigned long long d;
    asm("fma.rn.f32x2 %0, %1, %2, %3;" : "=l"(d) : "l"(a), "l"(b), "l"(c));
    return d;
}
__device__ __forceinline__ unsigned long long dup2(float v) {
    unsigned long long d;
    asm("mov.b64 %0, {%1, %1};" : "=l"(d) : "f"(v));
    return d;
}
__device__ __forceinline__ float2 unpack2(unsigned long long v) {
    float2 r;
    asm("mov.b64 {%0, %1}, %2;" : "=f"(r.x), "=f"(r.y) : "l"(v));
    return r;
}

// weight-row swizzle: group ocg at word off(ocg); LDS.64 within one instr
// (fixed j) hits 8 distinct bank-pairs -> conflict-free.
__device__ __host__ __forceinline__ int woff_of(int ocg) {
    return ocg * 8 + (ocg >> 2) * 2;
}

// ---------------------------------------------------------------------------
// Tiled conv3x3 + bias + relu. Block: 256 thr = 8 ocg x 32 pg.
// Tile: 64 oc x (TH x TW) px. Thread: 8 oc x 8 px (horizontal).
// ---------------------------------------------------------------------------
template <int CIN, int COUT, int CHUNK, int TH, int TW>
__global__ void __launch_bounds__(256, 2)
conv3x3_bias_relu(const float* __restrict__ in,
                  const float* __restrict__ wgt,
                  const float* __restrict__ bias,
                  float* __restrict__ out,
                  int H, int W)
{
    static_assert(CIN % CHUNK == 0, "CIN divisible by CHUNK");
    static_assert((TH * TW) == 256 && TW % 8 == 0, "tile = 256 px");
    constexpr int OCB = 64;
    constexpr int WROW = 68;            // >= woff_of(7)+8 = 66, even
    constexpr int IROW = TW + 2;
    constexpr int CG = TW / 8;          // col groups

    __shared__ __align__(16) float wsm[CHUNK][9][WROW];
    __shared__ float insm[CHUNK][TH + 2][IROW];

    const int tiles_x = W / TW;
    const int bx = (blockIdx.x % tiles_x) * TW;
    const int by = (blockIdx.x / tiles_x) * TH;
    const int n  = blockIdx.y;
    const int oc_base = blockIdx.z * OCB;

    const int tid = threadIdx.x;
    const int ocg = tid & 7;
    const int pg  = tid >> 3;           // 0..31
    const int row = pg / CG;            // 0..TH-1
    const int col = (pg % CG) * 8;      // 0,8,...
    const int woff = woff_of(ocg);

    // acc[op][p]: f32x2 lanes = (oc 2op, oc 2op+1) at pixel col+p
    unsigned long long acc[4][8];
    #pragma unroll
    for (int op = 0; op < 4; ++op)
        #pragma unroll
        for (int p = 0; p < 8; ++p) acc[op][p] = 0ull;

    #pragma unroll 1
    for (int c0 = 0; c0 < CIN; c0 += CHUNK) {
        // ---- weights: gmem (contiguous per oc) -> swizzled smem rows
        {
            const float* wg = wgt + (size_t)oc_base * CIN * 9 + (size_t)c0 * 9;
            constexpr int PER_OC = CHUNK * 9;
            constexpr int TOT = OCB * PER_OC;
            for (int idx = tid; idx < TOT; idx += 256) {
                int oc = idx / PER_OC;
                int r  = idx % PER_OC;                    // r = c*9 + k
                float v = wg[(size_t)oc * CIN * 9 + r];
                wsm[r / 9][r % 9][woff_of(oc >> 3) + (oc & 7)] = v;
            }
        }
        // ---- input tile: CHUNK x (TH+2) x (TW+2), zero-padded borders
        {
            constexpr int TILE2D = (TH + 2) * IROW;
            constexpr int TOT = CHUNK * TILE2D;
            for (int idx = tid; idx < TOT; idx += 256) {
                int c   = idx / TILE2D;
                int rem = idx % TILE2D;
                int iy  = rem / IROW;
                int ix  = rem % IROW;
                int gy = by + iy - 1;
                int gx = bx + ix - 1;
                float v = 0.0f;
                if (gy >= 0 && gy < H && gx >= 0 && gx < W)
                    v = in[(((size_t)n * CIN + c0 + c) * H + gy) * W + gx];
                insm[c][iy][ix] = v;
            }
        }
        __syncthreads();

        // ---- compute
        #pragma unroll 1
        for (int c = 0; c < CHUNK; ++c) {
            #pragma unroll
            for (int ky = 0; ky < 3; ++ky) {
                const float* rp = &insm[c][row + ky][col];
                unsigned long long d[10];
                #pragma unroll
                for (int i = 0; i < 10; ++i) d[i] = dup2(rp[i]);
                #pragma unroll
                for (int kx = 0; kx < 3; ++kx) {
                    const float* wp = &wsm[c][ky * 3 + kx][woff];
                    unsigned long long w2[4];
                    #pragma unroll
                    for (int j = 0; j < 4; ++j)
                        w2[j] = *reinterpret_cast<const unsigned long long*>(wp + 2 * j);
                    #pragma unroll
                    for (int op = 0; op < 4; ++op)
                        #pragma unroll
                        for (int p = 0; p < 8; ++p)
                            acc[op][p] = fma2(w2[op], d[kx + p], acc[op][p]);
                }
            }
        }
        __syncthreads();
    }

    // ---- epilogue: bias + relu, float4 stores per oc row
    const int gy = by + row;
    const int gx = bx + col;
    #pragma unroll
    for (int op = 0; op < 4; ++op) {
        const int oc0 = oc_base + ocg * 8 + 2 * op;
        const float b0 = bias[oc0];
        const float b1 = bias[oc0 + 1];
        float lo[8], hi[8];
        #pragma unroll
        for (int p = 0; p < 8; ++p) {
            float2 u = unpack2(acc[op][p]);
            lo[p] = fmaxf(u.x + b0, 0.0f);
            hi[p] = fmaxf(u.y + b1, 0.0f);
        }
        float* dst0 = out + (((size_t)n * COUT + oc0) * H + gy) * W + gx;
        float* dst1 = dst0 + (size_t)H * W;
        *reinterpret_cast<float4*>(dst0)     = make_float4(lo[0], lo[1], lo[2], lo[3]);
        *reinterpret_cast<float4*>(dst0 + 4) = make_float4(lo[4], lo[5], lo[6], lo[7]);
        *reinterpret_cast<float4*>(dst1)     = make_float4(hi[0], hi[1], hi[2], hi[3]);
        *reinterpret_cast<float4*>(dst1 + 4) = make_float4(hi[4], hi[5], hi[6], hi[7]);
    }
}

// ---------------------------------------------------------------------------
// 2x2 maxpool, NCHW.
// ---------------------------------------------------------------------------
__global__ void maxpool2x2(const float* __restrict__ in,
                           float* __restrict__ out,
                           int total, int C, int Ho, int Wo)
{
    int idx = blockIdx.x * blockDim.x + threadIdx.x;
    if (idx >= total) return;
    int x = idx % Wo;
    int y = (idx / Wo) % Ho;
    int rest = idx / (Wo * Ho);
    const int Wi = 2 * Wo;
    const float* p = in + ((size_t)rest * (2 * Ho) + 2 * y) * Wi + 2 * x;
    float m = fmaxf(fmaxf(p[0], p[1]), fmaxf(p[Wi], p[Wi + 1]));
    out[idx] = m;
}

// ---------------------------------------------------------------------------
template <int CIN, int COUT, int CHUNK, int TH, int TW>
static inline void launch_conv(const float* in, const float* w, const float* b,
                               float* out, int H, int W, int N)
{
    dim3 grid((W / TW) * (H / TH), N, COUT / 64);
    conv3x3_bias_relu<CIN, COUT, CHUNK, TH, TW><<<grid, 256>>>(in, w, b, out, H, W);
}

static inline void launch_pool(const float* in, float* out, int N, int C, int Hi, int Wi)
{
    int Ho = Hi / 2, Wo = Wi / 2;
    int total = N * C * Ho * Wo;
    maxpool2x2<<<(total + 255) / 256, 256>>>(in, out, total, C, Ho, Wo);
}

extern "C" void kernel_launch(void* const* d_in, const int* in_sizes, int n_in,
                              void* d_out, int out_size)
{
    (void)in_sizes; (void)n_in; (void)out_size;

    const float* x = (const float*)d_in[0];          // (2,3,384,384)
    const float* w[11];
    const float* b[11];
    for (int k = 1; k <= 10; ++k) {
        w[k] = (const float*)d_in[2 + 2 * (k - 1)];
        b[k] = (const float*)d_in[3 + 2 * (k - 1)];
    }

    float* A;
    float* Bb;
    cudaGetSymbolAddress((void**)&A,  g_bufA);
    cudaGetSymbolAddress((void**)&Bb, g_bufB);
    float* O = (float*)d_out;
    const int N = 2;

    // Stage 1 @ 384x384  (tiles 8x32)
    launch_conv<3,   64, 3, 8, 32>(x,  w[1], b[1], A,  384, 384, N);
    launch_conv<64,  64, 8, 8, 32>(A,  w[2], b[2], Bb, 384, 384, N);
    launch_pool(Bb, A, N, 64, 384, 384);              // -> 192x192

    // Stage 2 @ 192x192
    launch_conv<64, 128, 8, 8, 32>(A,  w[3], b[3], Bb, 192, 192, N);
    launch_conv<128,128, 8, 8, 32>(Bb, w[4], b[4], A,  192, 192, N);
    launch_pool(A, Bb, N, 128, 192, 192);             // -> 96x96

    // Stage 3 @ 96x96
    launch_conv<128,256, 8, 8, 32>(Bb, w[5], b[5], A,  96, 96, N);
    launch_conv<256,256, 8, 8, 32>(A,  w[6], b[6], Bb, 96, 96, N);
    launch_conv<256,256, 8, 8, 32>(Bb, w[7], b[7], A,  96, 96, N);
    launch_pool(A, Bb, N, 256, 96, 96);               // -> 48x48

    // Stage 4 @ 48x48   (tiles 16x16)
    launch_conv<256,512, 8, 16, 16>(Bb, w[8],  b[8],  A,  48, 48, N);
    launch_conv<512,512, 8, 16, 16>(A,  w[9],  b[9],  Bb, 48, 48, N);
    launch_conv<512,512, 8, 16, 16>(Bb, w[10], b[10], O,  48, 48, N);
}